// round 5
// baseline (speedup 1.0000x reference)
#include <cuda_runtime.h>
#include <cuda_bf16.h>
#include <math.h>

// Problem constants
#define N_VOTERS   1048576
#define N_SEG      4096
#define N_CAND     32
#define EMB        128
#define TILE_M     64          // voters per tile
#define N_TILES    (N_VOTERS / TILE_M)   // 16384
#define HPAD       132         // padded row stride for h buffers (floats)

// 2 MB aggregation scratch (device global; no allocation allowed)
__device__ float g_agg[N_SEG * EMB];

// ---------------------------------------------------------------------------
// Shared memory layouts
// ---------------------------------------------------------------------------
struct Smem1 {
    float W1[32 * 128];      // 16 KB
    float W2[128 * 128];     // 64 KB
    float W3[128 * 128];     // 64 KB
    float b1[128], b2[128], b3[128];
    float xs[TILE_M * 32];   // 8 KB  (contiguous tile of x)
    float h1[TILE_M * HPAD]; // 33 KB
    float h2[TILE_M * HPAD]; // 33 KB
    int   idxs[TILE_M];
};

struct Smem2 {
    float W1[128 * 128];     // 64 KB
    float W2[128 * 128];     // 64 KB
    float W3[128 * 32];      // 16 KB
    float b1[128], b2[128], b3[32];
    float B0[TILE_M * HPAD];
    float B1[TILE_M * HPAD];
    float sc[TILE_M * 33];   // scores, padded stride 33
};

// ---------------------------------------------------------------------------
// 64x128 GEMM microkernel: B[64,128] = act(A[64,K] @ W[K,128] + bias)
// 256 threads: rowg = t>>4 (4 rows each), colg = t&15 (8 cols each)
// ---------------------------------------------------------------------------
template<int K, int SA, bool RELU>
__device__ __forceinline__ void gemm128(const float* __restrict__ A,
                                        const float* __restrict__ W,
                                        const float* __restrict__ bias,
                                        float* __restrict__ B,
                                        int rowg, int colg)
{
    float acc[4][8];
    {
        float4 bv0 = *(const float4*)&bias[colg * 8];
        float4 bv1 = *(const float4*)&bias[colg * 8 + 4];
        #pragma unroll
        for (int i = 0; i < 4; ++i) {
            acc[i][0] = bv0.x; acc[i][1] = bv0.y; acc[i][2] = bv0.z; acc[i][3] = bv0.w;
            acc[i][4] = bv1.x; acc[i][5] = bv1.y; acc[i][6] = bv1.z; acc[i][7] = bv1.w;
        }
    }

    #pragma unroll 2
    for (int k0 = 0; k0 < K; k0 += 4) {
        float a[4][4];
        #pragma unroll
        for (int i = 0; i < 4; ++i) {
            float4 v = *(const float4*)&A[(rowg * 4 + i) * SA + k0];
            a[i][0] = v.x; a[i][1] = v.y; a[i][2] = v.z; a[i][3] = v.w;
        }
        #pragma unroll
        for (int kk = 0; kk < 4; ++kk) {
            float4 w0 = *(const float4*)&W[(k0 + kk) * 128 + colg * 8];
            float4 w1 = *(const float4*)&W[(k0 + kk) * 128 + colg * 8 + 4];
            float wv[8] = {w0.x, w0.y, w0.z, w0.w, w1.x, w1.y, w1.z, w1.w};
            #pragma unroll
            for (int i = 0; i < 4; ++i) {
                #pragma unroll
                for (int j = 0; j < 8; ++j)
                    acc[i][j] += a[i][kk] * wv[j];
            }
        }
    }

    #pragma unroll
    for (int i = 0; i < 4; ++i) {
        float o[8];
        #pragma unroll
        for (int j = 0; j < 8; ++j)
            o[j] = RELU ? fmaxf(acc[i][j], 0.0f) : acc[i][j];
        float* dst = &B[(rowg * 4 + i) * HPAD + colg * 8];
        *(float4*)dst       = make_float4(o[0], o[1], o[2], o[3]);
        *(float4*)(dst + 4) = make_float4(o[4], o[5], o[6], o[7]);
    }
}

// ---------------------------------------------------------------------------
// Kernel 0: zero the aggregation buffer
// ---------------------------------------------------------------------------
__global__ void zero_agg_kernel()
{
    int i = blockIdx.x * blockDim.x + threadIdx.x;
    if (i < N_SEG * EMB) g_agg[i] = 0.0f;
}

// ---------------------------------------------------------------------------
// Kernel 1: fused local MLP + sorted segment-sum
// ---------------------------------------------------------------------------
__global__ __launch_bounds__(256, 1)
void local_kernel(const float* __restrict__ x,
                  const int* __restrict__ index,
                  const float* __restrict__ lW1, const float* __restrict__ lb1,
                  const float* __restrict__ lW2, const float* __restrict__ lb2,
                  const float* __restrict__ lW3, const float* __restrict__ lb3)
{
    extern __shared__ char raw[];
    Smem1& s = *reinterpret_cast<Smem1*>(raw);
    const int t = threadIdx.x;

    // Load all weights / biases once per block
    for (int i = t * 4; i < 32 * 128;  i += 1024) *(float4*)&s.W1[i] = *(const float4*)&lW1[i];
    for (int i = t * 4; i < 128 * 128; i += 1024) *(float4*)&s.W2[i] = *(const float4*)&lW2[i];
    for (int i = t * 4; i < 128 * 128; i += 1024) *(float4*)&s.W3[i] = *(const float4*)&lW3[i];
    if (t < 128) { s.b1[t] = lb1[t]; s.b2[t] = lb2[t]; s.b3[t] = lb3[t]; }
    __syncthreads();

    const int colg = t & 15;
    const int rowg = t >> 4;

    for (int tile = blockIdx.x; tile < N_TILES; tile += gridDim.x) {
        const int r0 = tile * TILE_M;

        // x tile is a contiguous run of 64*32 floats
        for (int i = t * 4; i < TILE_M * 32; i += 1024)
            *(float4*)&s.xs[i] = *(const float4*)&x[(size_t)r0 * 32 + i];
        if (t < TILE_M) s.idxs[t] = index[r0 + t];
        __syncthreads();

        gemm128<32, 32, true>(s.xs, s.W1, s.b1, s.h1, rowg, colg);
        __syncthreads();
        gemm128<128, HPAD, true>(s.h1, s.W2, s.b2, s.h2, rowg, colg);
        __syncthreads();
        gemm128<128, HPAD, false>(s.h2, s.W3, s.b3, s.h1, rowg, colg);
        __syncthreads();

        // Sorted segment reduction: thread t handles column (t&127),
        // rows [half*32, half*32+32)
        {
            const int col  = t & 127;
            const int half = t >> 7;
            const int base = half * 32;
            float run = 0.0f;
            int cur = s.idxs[base];
            #pragma unroll 4
            for (int r = 0; r < 32; ++r) {
                int sg  = s.idxs[base + r];
                float v = s.h1[(base + r) * HPAD + col];
                if (sg != cur) {
                    atomicAdd(&g_agg[cur * EMB + col], run);
                    run = 0.0f;
                    cur = sg;
                }
                run += v;
            }
            atomicAdd(&g_agg[cur * EMB + col], run);
        }
        __syncthreads();
    }
}

// ---------------------------------------------------------------------------
// Kernel 2: global MLP + log_softmax over 4096 segments
// grid = 64 blocks x 64 segments
// ---------------------------------------------------------------------------
__global__ __launch_bounds__(256, 1)
void global_kernel(const float* __restrict__ gW1, const float* __restrict__ gb1,
                   const float* __restrict__ gW2, const float* __restrict__ gb2,
                   const float* __restrict__ gW3, const float* __restrict__ gb3,
                   float* __restrict__ out)
{
    extern __shared__ char raw[];
    Smem2& s = *reinterpret_cast<Smem2*>(raw);
    const int t = threadIdx.x;

    for (int i = t * 4; i < 128 * 128; i += 1024) *(float4*)&s.W1[i] = *(const float4*)&gW1[i];
    for (int i = t * 4; i < 128 * 128; i += 1024) *(float4*)&s.W2[i] = *(const float4*)&gW2[i];
    for (int i = t * 4; i < 128 * 32;  i += 1024) *(float4*)&s.W3[i] = *(const float4*)&gW3[i];
    if (t < 128) { s.b1[t] = gb1[t]; s.b2[t] = gb2[t]; }
    if (t < 32)  { s.b3[t] = gb3[t]; }

    const int seg0 = blockIdx.x * TILE_M;

    // Load aggregated tile [64,128] into B0 (padded)
    for (int i = t * 4; i < TILE_M * 128; i += 1024) {
        int row = i >> 7, c = i & 127;
        *(float4*)&s.B0[row * HPAD + c] = *(const float4*)&g_agg[(seg0 + row) * EMB + c];
    }
    __syncthreads();

    const int colg = t & 15;
    const int rowg = t >> 4;

    gemm128<128, HPAD, true>(s.B0, s.W1, s.b1, s.B1, rowg, colg);
    __syncthreads();
    gemm128<128, HPAD, true>(s.B1, s.W2, s.b2, s.B0, rowg, colg);
    __syncthreads();

    // Layer 3: [64,128] @ [128,32] -> scores [64,32]
    {
        const int rowg3 = t >> 3;   // 0..31, 2 rows each
        const int colg3 = t & 7;    // 0..7, 4 cols each
        float acc[2][4];
        {
            float4 bv = *(const float4*)&s.b3[colg3 * 4];
            #pragma unroll
            for (int i = 0; i < 2; ++i) {
                acc[i][0] = bv.x; acc[i][1] = bv.y; acc[i][2] = bv.z; acc[i][3] = bv.w;
            }
        }
        #pragma unroll 2
        for (int k0 = 0; k0 < 128; k0 += 4) {
            float a[2][4];
            #pragma unroll
            for (int i = 0; i < 2; ++i) {
                float4 v = *(const float4*)&s.B0[(rowg3 * 2 + i) * HPAD + k0];
                a[i][0] = v.x; a[i][1] = v.y; a[i][2] = v.z; a[i][3] = v.w;
            }
            #pragma unroll
            for (int kk = 0; kk < 4; ++kk) {
                float4 w = *(const float4*)&s.W3[(k0 + kk) * 32 + colg3 * 4];
                float wv[4] = {w.x, w.y, w.z, w.w};
                #pragma unroll
                for (int i = 0; i < 2; ++i) {
                    #pragma unroll
                    for (int j = 0; j < 4; ++j)
                        acc[i][j] += a[i][kk] * wv[j];
                }
            }
        }
        #pragma unroll
        for (int i = 0; i < 2; ++i)
            #pragma unroll
            for (int j = 0; j < 4; ++j)
                s.sc[(rowg3 * 2 + i) * 33 + colg3 * 4 + j] = acc[i][j];
    }
    __syncthreads();

    // log_softmax per row; thread r handles row r (padded stride 33 avoids conflicts)
    if (t < TILE_M) {
        float v[32];
        float m = -INFINITY;
        #pragma unroll
        for (int c = 0; c < 32; ++c) { v[c] = s.sc[t * 33 + c]; m = fmaxf(m, v[c]); }
        float sum = 0.0f;
        #pragma unroll
        for (int c = 0; c < 32; ++c) sum += expf(v[c] - m);
        float lse = m + logf(sum);
        float* dst = &out[(size_t)(seg0 + t) * 32];
        #pragma unroll
        for (int c = 0; c < 32; ++c) dst[c] = v[c] - lse;
    }
}

// ---------------------------------------------------------------------------
// Launch
// ---------------------------------------------------------------------------
extern "C" void kernel_launch(void* const* d_in, const int* in_sizes, int n_in,
                              void* d_out, int out_size)
{
    const float* x     = (const float*)d_in[0];
    const int*   index = (const int*)d_in[1];   // int32: JAX x64 is disabled, astype(int64) is a no-op
    const float* lW1 = (const float*)d_in[2];
    const float* lb1 = (const float*)d_in[3];
    const float* lW2 = (const float*)d_in[4];
    const float* lb2 = (const float*)d_in[5];
    const float* lW3 = (const float*)d_in[6];
    const float* lb3 = (const float*)d_in[7];
    const float* gW1 = (const float*)d_in[8];
    const float* gb1 = (const float*)d_in[9];
    const float* gW2 = (const float*)d_in[10];
    const float* gb2 = (const float*)d_in[11];
    const float* gW3 = (const float*)d_in[12];
    const float* gb3 = (const float*)d_in[13];
    float* out = (float*)d_out;

    cudaFuncSetAttribute((const void*)local_kernel,
                         cudaFuncAttributeMaxDynamicSharedMemorySize, (int)sizeof(Smem1));
    cudaFuncSetAttribute((const void*)global_kernel,
                         cudaFuncAttributeMaxDynamicSharedMemorySize, (int)sizeof(Smem2));

    zero_agg_kernel<<<(N_SEG * EMB) / 256, 256>>>();
    local_kernel<<<296, 256, sizeof(Smem1)>>>(x, index, lW1, lb1, lW2, lb2, lW3, lb3);
    global_kernel<<<N_SEG / TILE_M, 256, sizeof(Smem2)>>>(gW1, gb1, gW2, gb2, gW3, gb3, out);
}

// round 7
// speedup vs baseline: 5.5113x; 5.5113x over previous
#include <cuda_runtime.h>
#include <cuda_fp16.h>
#include <math.h>
#include <stdint.h>

// ---------------------------------------------------------------------------
// Problem constants
// ---------------------------------------------------------------------------
#define N_VOTERS   1048576
#define N_SEG      4096
#define EMB        128
#define TILE       128                     // voters per tile
#define NT         (N_VOTERS / TILE)       // 8192 tiles
#define XS         40                      // row stride (halves) for K=32 bufs
#define HS         136                     // row stride (halves) for K=128 bufs
#define HPAD       132

__device__ float g_agg[N_SEG * EMB];

// ---------------------------------------------------------------------------
// SMEM layout (byte offsets, all 16B aligned)
// ---------------------------------------------------------------------------
#define SM_W1   0        // [128][XS] half : 10240
#define SM_W2   10240    // [128][HS] half : 34816
#define SM_W3   45056    // [128][HS] half : 34816
#define SM_XS   79872    // [128][XS] half : 10240
#define SM_H    90112    // [128][HS] half : 34816
#define SM_SCR  124928   // [128][128] f32 : 65536
#define SM_B1   190464
#define SM_B2   190976
#define SM_B3   191488
#define SM_IDX  192000
#define SM_SZ   192512

static __device__ __forceinline__ uint32_t s2u(const void* p) {
    uint32_t a;
    asm("{ .reg .u64 t; cvta.to.shared.u64 t, %1; cvt.u32.u64 %0, t; }" : "=r"(a) : "l"(p));
    return a;
}

static __device__ __forceinline__ void ldsm4(uint32_t* r, uint32_t addr) {
    asm volatile("ldmatrix.sync.aligned.m8n8.x4.shared.b16 {%0,%1,%2,%3}, [%4];"
                 : "=r"(r[0]), "=r"(r[1]), "=r"(r[2]), "=r"(r[3]) : "r"(addr));
}

static __device__ __forceinline__ void mma16816(float* d, const uint32_t* a,
                                                uint32_t b0, uint32_t b1) {
    asm volatile("mma.sync.aligned.m16n8k16.row.col.f32.f16.f16.f32 "
                 "{%0,%1,%2,%3}, {%4,%5,%6,%7}, {%8,%9}, {%0,%1,%2,%3};"
                 : "+f"(d[0]), "+f"(d[1]), "+f"(d[2]), "+f"(d[3])
                 : "r"(a[0]), "r"(a[1]), "r"(a[2]), "r"(a[3]), "r"(b0), "r"(b1));
}

// ---------------------------------------------------------------------------
// One MLP layer on a 128-row tile, warp-local rows [16w, 16w+16).
// A: fp16 [rows][K] row-major (stride STA halves), warp's base passed in.
// B: fp16 [N=128][K] (stride STB halves) — "col" operand of mma.
// KCH = K/16 chunks. Output: hidden -> fp16 h (stride HS); last -> f32 scr.
// ---------------------------------------------------------------------------
template<int KCH, int STA, int STB, bool RELU, bool LAST>
static __device__ __forceinline__ void layer_mma(uint32_t aAddr, uint32_t bAddr,
                                                 const float* __restrict__ bias,
                                                 uint32_t outAddr, int lane)
{
    const int l7 = lane & 7, lq = (lane >> 3) & 1, lh = lane >> 4;

    // ldmatrix lane-address bases (bytes)
    const uint32_t aRow = aAddr + (uint32_t)((l7 + lq * 8) * STA) * 2u + (uint32_t)lh * 16u;
    const uint32_t bRow = bAddr + (uint32_t)((l7 + lh * 8) * STB) * 2u + (uint32_t)lq * 16u;

    float d[16][4];
    #pragma unroll
    for (int n = 0; n < 16; ++n)
        #pragma unroll
        for (int j = 0; j < 4; ++j) d[n][j] = 0.0f;

    #pragma unroll
    for (int kc = 0; kc < KCH; ++kc) {
        uint32_t a[4];
        ldsm4(a, aRow + (uint32_t)kc * 32u);
        #pragma unroll
        for (int p = 0; p < 8; ++p) {           // pairs of n-tiles (16 N-rows each)
            uint32_t b[4];
            ldsm4(b, bRow + (uint32_t)p * (32u * STB) + (uint32_t)kc * 32u);
            mma16816(d[2 * p],     a, b[0], b[1]);
            mma16816(d[2 * p + 1], a, b[2], b[3]);
        }
    }

    // epilogue: bias (+ReLU) ; rows r = lane>>2 and +8 of the warp's 16
    const int r = lane >> 2, cq = 2 * (lane & 3);
    #pragma unroll
    for (int n = 0; n < 16; ++n) {
        const int c0 = n * 8 + cq;
        float v0 = d[n][0] + bias[c0], v1 = d[n][1] + bias[c0 + 1];
        float v2 = d[n][2] + bias[c0], v3 = d[n][3] + bias[c0 + 1];
        if (RELU) {
            v0 = fmaxf(v0, 0.f); v1 = fmaxf(v1, 0.f);
            v2 = fmaxf(v2, 0.f); v3 = fmaxf(v3, 0.f);
        }
        if (LAST) {
            // f32 scr, stride 128 floats
            uint32_t o0 = outAddr + (uint32_t)(r * 128 + c0) * 4u;
            uint32_t o1 = outAddr + (uint32_t)((r + 8) * 128 + c0) * 4u;
            asm volatile("st.shared.v2.f32 [%0], {%1,%2};" :: "r"(o0), "f"(v0), "f"(v1) : "memory");
            asm volatile("st.shared.v2.f32 [%0], {%1,%2};" :: "r"(o1), "f"(v2), "f"(v3) : "memory");
        } else {
            __half2 p0 = __floats2half2_rn(v0, v1);
            __half2 p1 = __floats2half2_rn(v2, v3);
            uint32_t o0 = outAddr + (uint32_t)(r * HS + c0) * 2u;
            uint32_t o1 = outAddr + (uint32_t)((r + 8) * HS + c0) * 2u;
            asm volatile("st.shared.b32 [%0], %1;" :: "r"(o0), "r"(*(uint32_t*)&p0) : "memory");
            asm volatile("st.shared.b32 [%0], %1;" :: "r"(o1), "r"(*(uint32_t*)&p1) : "memory");
        }
    }
}

// ---------------------------------------------------------------------------
// Kernel 0: zero agg buffer
// ---------------------------------------------------------------------------
__global__ void zero_agg_kernel() {
    int i = blockIdx.x * blockDim.x + threadIdx.x;
    if (i < N_SEG * EMB) g_agg[i] = 0.0f;
}

// ---------------------------------------------------------------------------
// Kernel 1: fp16 mma.sync local MLP + sorted segment-sum (persistent)
// ---------------------------------------------------------------------------
__global__ __launch_bounds__(256, 1)
void local_mma(const float* __restrict__ x,
               const int* __restrict__ index,
               const float* __restrict__ lW1, const float* __restrict__ lb1,
               const float* __restrict__ lW2, const float* __restrict__ lb2,
               const float* __restrict__ lW3, const float* __restrict__ lb3)
{
    extern __shared__ __align__(1024) char sm[];
    const uint32_t sb = s2u(sm);
    const int t = threadIdx.x;
    const int w = t >> 5, lane = t & 31;

    __half* W1t = (__half*)(sm + SM_W1);
    __half* W2t = (__half*)(sm + SM_W2);
    __half* W3t = (__half*)(sm + SM_W3);
    float*  fb1 = (float*)(sm + SM_B1);
    float*  fb2 = (float*)(sm + SM_B2);
    float*  fb3 = (float*)(sm + SM_B3);
    int*    idxs = (int*)(sm + SM_IDX);
    float*  scr = (float*)(sm + SM_SCR);

    // one-time: transpose + fp16-convert weights ([k][n] gmem -> [n][k] smem)
    for (int i = t; i < 32 * 128; i += 256) {
        int k = i >> 7, n = i & 127;
        W1t[n * XS + k] = __float2half_rn(lW1[i]);
    }
    for (int i = t; i < 128 * 128; i += 256) {
        int k = i >> 7, n = i & 127;
        W2t[n * HS + k] = __float2half_rn(lW2[i]);
        W3t[n * HS + k] = __float2half_rn(lW3[i]);
    }
    if (t < 128) { fb1[t] = lb1[t]; fb2[t] = lb2[t]; fb3[t] = lb3[t]; }
    __syncthreads();

    const uint32_t xsW   = sb + SM_XS + (uint32_t)(16 * w * XS) * 2u;  // warp's x rows
    const uint32_t hW    = sb + SM_H  + (uint32_t)(16 * w * HS) * 2u;  // warp's h rows
    const uint32_t scrW  = sb + SM_SCR + (uint32_t)(16 * w * 128) * 4u;
    const uint32_t w1A   = sb + SM_W1;
    const uint32_t w2A   = sb + SM_W2;
    const uint32_t w3A   = sb + SM_W3;

    for (int tile = blockIdx.x; tile < NT; tile += gridDim.x) {
        const int r0 = tile * TILE;

        // load warp's 16 rows of x [16][32] f32 -> fp16 SMEM (stride XS)
        #pragma unroll
        for (int j = 0; j < 4; ++j) {
            int f = lane + 32 * j;                 // float4 id in [0,128)
            int row = f >> 3, c4 = f & 7;          // row in warp tile, float4-col
            float4 v = *(const float4*)&x[((size_t)(r0 + 16 * w + row)) * 32 + c4 * 4];
            __half2 h0 = __floats2half2_rn(v.x, v.y);
            __half2 h1 = __floats2half2_rn(v.z, v.w);
            uint32_t o = xsW + (uint32_t)(row * XS + c4 * 4) * 2u;
            asm volatile("st.shared.v2.b32 [%0], {%1,%2};"
                         :: "r"(o), "r"(*(uint32_t*)&h0), "r"(*(uint32_t*)&h1) : "memory");
        }
        if (t < 128) idxs[t] = index[r0 + t];
        __syncwarp();

        // layer 1: K=32 (A stride XS, B=W1t stride XS)
        layer_mma<2, XS, XS, true,  false>(xsW, w1A, fb1, hW, lane);
        __syncwarp();
        // layer 2: K=128
        layer_mma<8, HS, HS, true,  false>(hW, w2A, fb2, hW, lane);
        __syncwarp();
        // layer 3: K=128, f32 out to scr
        layer_mma<8, HS, HS, false, true >(hW, w3A, fb3, scrW, lane);
        __syncthreads();

        // sorted segment reduction: thread = column (t&127), half = t>>7
        {
            const int col  = t & 127;
            const int half = t >> 7;
            const int base = half * 64;
            float run = 0.0f;
            int cur = idxs[base];
            #pragma unroll 4
            for (int r = 0; r < 64; ++r) {
                int sg  = idxs[base + r];
                float v = scr[(base + r) * 128 + col];
                if (sg != cur) {
                    atomicAdd(&g_agg[cur * EMB + col], run);
                    run = 0.0f; cur = sg;
                }
                run += v;
            }
            atomicAdd(&g_agg[cur * EMB + col], run);
        }
        __syncthreads();
    }
}

// ---------------------------------------------------------------------------
// Kernel 2: global MLP + log_softmax (fp32, unchanged from passing R5)
// ---------------------------------------------------------------------------
struct Smem2 {
    float W1[128 * 128];
    float W2[128 * 128];
    float W3[128 * 32];
    float b1[128], b2[128], b3[32];
    float B0[64 * HPAD];
    float B1[64 * HPAD];
    float sc[64 * 33];
};

template<int K, int SA, bool RELU>
__device__ __forceinline__ void gemm128(const float* __restrict__ A,
                                        const float* __restrict__ W,
                                        const float* __restrict__ bias,
                                        float* __restrict__ B,
                                        int rowg, int colg)
{
    float acc[4][8];
    {
        float4 bv0 = *(const float4*)&bias[colg * 8];
        float4 bv1 = *(const float4*)&bias[colg * 8 + 4];
        #pragma unroll
        for (int i = 0; i < 4; ++i) {
            acc[i][0] = bv0.x; acc[i][1] = bv0.y; acc[i][2] = bv0.z; acc[i][3] = bv0.w;
            acc[i][4] = bv1.x; acc[i][5] = bv1.y; acc[i][6] = bv1.z; acc[i][7] = bv1.w;
        }
    }
    #pragma unroll 2
    for (int k0 = 0; k0 < K; k0 += 4) {
        float a[4][4];
        #pragma unroll
        for (int i = 0; i < 4; ++i) {
            float4 v = *(const float4*)&A[(rowg * 4 + i) * SA + k0];
            a[i][0] = v.x; a[i][1] = v.y; a[i][2] = v.z; a[i][3] = v.w;
        }
        #pragma unroll
        for (int kk = 0; kk < 4; ++kk) {
            float4 w0 = *(const float4*)&W[(k0 + kk) * 128 + colg * 8];
            float4 w1 = *(const float4*)&W[(k0 + kk) * 128 + colg * 8 + 4];
            float wv[8] = {w0.x, w0.y, w0.z, w0.w, w1.x, w1.y, w1.z, w1.w};
            #pragma unroll
            for (int i = 0; i < 4; ++i)
                #pragma unroll
                for (int j = 0; j < 8; ++j)
                    acc[i][j] += a[i][kk] * wv[j];
        }
    }
    #pragma unroll
    for (int i = 0; i < 4; ++i) {
        float o[8];
        #pragma unroll
        for (int j = 0; j < 8; ++j)
            o[j] = RELU ? fmaxf(acc[i][j], 0.0f) : acc[i][j];
        float* dst = &B[(rowg * 4 + i) * HPAD + colg * 8];
        *(float4*)dst       = make_float4(o[0], o[1], o[2], o[3]);
        *(float4*)(dst + 4) = make_float4(o[4], o[5], o[6], o[7]);
    }
}

__global__ __launch_bounds__(256, 1)
void global_kernel(const float* __restrict__ gW1, const float* __restrict__ gb1,
                   const float* __restrict__ gW2, const float* __restrict__ gb2,
                   const float* __restrict__ gW3, const float* __restrict__ gb3,
                   float* __restrict__ out)
{
    extern __shared__ char raw[];
    Smem2& s = *reinterpret_cast<Smem2*>(raw);
    const int t = threadIdx.x;

    for (int i = t * 4; i < 128 * 128; i += 1024) *(float4*)&s.W1[i] = *(const float4*)&gW1[i];
    for (int i = t * 4; i < 128 * 128; i += 1024) *(float4*)&s.W2[i] = *(const float4*)&gW2[i];
    for (int i = t * 4; i < 128 * 32;  i += 1024) *(float4*)&s.W3[i] = *(const float4*)&gW3[i];
    if (t < 128) { s.b1[t] = gb1[t]; s.b2[t] = gb2[t]; }
    if (t < 32)  { s.b3[t] = gb3[t]; }

    const int seg0 = blockIdx.x * 64;

    for (int i = t * 4; i < 64 * 128; i += 1024) {
        int row = i >> 7, c = i & 127;
        *(float4*)&s.B0[row * HPAD + c] = *(const float4*)&g_agg[(seg0 + row) * EMB + c];
    }
    __syncthreads();

    const int colg = t & 15;
    const int rowg = t >> 4;

    gemm128<128, HPAD, true>(s.B0, s.W1, s.b1, s.B1, rowg, colg);
    __syncthreads();
    gemm128<128, HPAD, true>(s.B1, s.W2, s.b2, s.B0, rowg, colg);
    __syncthreads();

    {
        const int rowg3 = t >> 3;
        const int colg3 = t & 7;
        float acc[2][4];
        {
            float4 bv = *(const float4*)&s.b3[colg3 * 4];
            #pragma unroll
            for (int i = 0; i < 2; ++i) {
                acc[i][0] = bv.x; acc[i][1] = bv.y; acc[i][2] = bv.z; acc[i][3] = bv.w;
            }
        }
        #pragma unroll 2
        for (int k0 = 0; k0 < 128; k0 += 4) {
            float a[2][4];
            #pragma unroll
            for (int i = 0; i < 2; ++i) {
                float4 v = *(const float4*)&s.B0[(rowg3 * 2 + i) * HPAD + k0];
                a[i][0] = v.x; a[i][1] = v.y; a[i][2] = v.z; a[i][3] = v.w;
            }
            #pragma unroll
            for (int kk = 0; kk < 4; ++kk) {
                float4 w = *(const float4*)&s.W3[(k0 + kk) * 32 + colg3 * 4];
                float wv[4] = {w.x, w.y, w.z, w.w};
                #pragma unroll
                for (int i = 0; i < 2; ++i)
                    #pragma unroll
                    for (int j = 0; j < 4; ++j)
                        acc[i][j] += a[i][kk] * wv[j];
            }
        }
        #pragma unroll
        for (int i = 0; i < 2; ++i)
            #pragma unroll
            for (int j = 0; j < 4; ++j)
                s.sc[(rowg3 * 2 + i) * 33 + colg3 * 4 + j] = acc[i][j];
    }
    __syncthreads();

    if (t < 64) {
        float v[32];
        float m = -INFINITY;
        #pragma unroll
        for (int c = 0; c < 32; ++c) { v[c] = s.sc[t * 33 + c]; m = fmaxf(m, v[c]); }
        float sum = 0.0f;
        #pragma unroll
        for (int c = 0; c < 32; ++c) sum += expf(v[c] - m);
        float lse = m + logf(sum);
        float* dst = &out[(size_t)(seg0 + t) * 32];
        #pragma unroll
        for (int c = 0; c < 32; ++c) dst[c] = v[c] - lse;
    }
}

// ---------------------------------------------------------------------------
// Launch
// ---------------------------------------------------------------------------
extern "C" void kernel_launch(void* const* d_in, const int* in_sizes, int n_in,
                              void* d_out, int out_size)
{
    const float* x     = (const float*)d_in[0];
    const int*   index = (const int*)d_in[1];
    const float* lW1 = (const float*)d_in[2];
    const float* lb1 = (const float*)d_in[3];
    const float* lW2 = (const float*)d_in[4];
    const float* lb2 = (const float*)d_in[5];
    const float* lW3 = (const float*)d_in[6];
    const float* lb3 = (const float*)d_in[7];
    const float* gW1 = (const float*)d_in[8];
    const float* gb1 = (const float*)d_in[9];
    const float* gW2 = (const float*)d_in[10];
    const float* gb2 = (const float*)d_in[11];
    const float* gW3 = (const float*)d_in[12];
    const float* gb3 = (const float*)d_in[13];
    float* out = (float*)d_out;

    cudaFuncSetAttribute((const void*)local_mma,
                         cudaFuncAttributeMaxDynamicSharedMemorySize, SM_SZ);
    cudaFuncSetAttribute((const void*)global_kernel,
                         cudaFuncAttributeMaxDynamicSharedMemorySize, (int)sizeof(Smem2));

    zero_agg_kernel<<<(N_SEG * EMB) / 256, 256>>>();
    local_mma<<<148, 256, SM_SZ>>>(x, index, lW1, lb1, lW2, lb2, lW3, lb3);
    global_kernel<<<N_SEG / 64, 256, sizeof(Smem2)>>>(gW1, gb1, gW2, gb2, gW3, gb3, out);
}

// round 8
// speedup vs baseline: 7.7423x; 1.4048x over previous
#include <cuda_runtime.h>
#include <cuda_fp16.h>
#include <math.h>
#include <stdint.h>

// ---------------------------------------------------------------------------
// Problem constants
// ---------------------------------------------------------------------------
#define N_VOTERS   1048576
#define N_SEG      4096
#define EMB        128
#define TILE       128                     // voters per tile
#define NT         (N_VOTERS / TILE)       // 8192 tiles
#define XS         40                      // row stride (halves) for K=32 bufs
#define HS         136                     // row stride (halves) for K=128 bufs
#define HPAD       132

__device__ float g_agg[N_SEG * EMB];

// ---------------------------------------------------------------------------
// SMEM layout (byte offsets, all 16B aligned). Two tile groups (g = 0,1).
// ---------------------------------------------------------------------------
#define SM_W1    0        // [128][XS] half : 10240
#define SM_W2    10240    // [128][HS] half : 34816
#define SM_W3    45056    // [128][HS] half : 34816
#define SM_XS    79872    // 2 x [128][XS] half : 20480
#define SM_H     100352   // 2 x [128][HS] half : 69632
#define SM_B1    169984
#define SM_B2    170496
#define SM_B3    171008
#define SM_IDX   171520   // 2 x 128 int
#define SM_SZ    172544

static __device__ __forceinline__ uint32_t s2u(const void* p) {
    uint32_t a;
    asm("{ .reg .u64 t; cvta.to.shared.u64 t, %1; cvt.u32.u64 %0, t; }" : "=r"(a) : "l"(p));
    return a;
}

static __device__ __forceinline__ void ldsm4(uint32_t* r, uint32_t addr) {
    asm volatile("ldmatrix.sync.aligned.m8n8.x4.shared.b16 {%0,%1,%2,%3}, [%4];"
                 : "=r"(r[0]), "=r"(r[1]), "=r"(r[2]), "=r"(r[3]) : "r"(addr));
}

static __device__ __forceinline__ void mma16816(float* d, const uint32_t* a,
                                                uint32_t b0, uint32_t b1) {
    asm volatile("mma.sync.aligned.m16n8k16.row.col.f32.f16.f16.f32 "
                 "{%0,%1,%2,%3}, {%4,%5,%6,%7}, {%8,%9}, {%0,%1,%2,%3};"
                 : "+f"(d[0]), "+f"(d[1]), "+f"(d[2]), "+f"(d[3])
                 : "r"(a[0]), "r"(a[1]), "r"(a[2]), "r"(a[3]), "r"(b0), "r"(b1));
}

// ---------------------------------------------------------------------------
// One MLP layer on a 128-row tile, warp-local rows [16wl, 16wl+16).
// A: fp16 [rows][K] row-major (stride STA halves), warp's base passed in.
// B: fp16 [N=128][K] (stride STB halves) — "col" operand of mma.
// Output: fp16 (stride HS) with optional ReLU.
// ---------------------------------------------------------------------------
template<int KCH, int STA, int STB, bool RELU>
static __device__ __forceinline__ void layer_mma(uint32_t aAddr, uint32_t bAddr,
                                                 const float* __restrict__ bias,
                                                 uint32_t outAddr, int lane)
{
    const int l7 = lane & 7, lq = (lane >> 3) & 1, lh = lane >> 4;

    const uint32_t aRow = aAddr + (uint32_t)((l7 + lq * 8) * STA) * 2u + (uint32_t)lh * 16u;
    const uint32_t bRow = bAddr + (uint32_t)((l7 + lh * 8) * STB) * 2u + (uint32_t)lq * 16u;

    float d[16][4];
    #pragma unroll
    for (int n = 0; n < 16; ++n)
        #pragma unroll
        for (int j = 0; j < 4; ++j) d[n][j] = 0.0f;

    #pragma unroll
    for (int kc = 0; kc < KCH; ++kc) {
        uint32_t a[4];
        ldsm4(a, aRow + (uint32_t)kc * 32u);
        #pragma unroll
        for (int p = 0; p < 8; ++p) {
            uint32_t b[4];
            ldsm4(b, bRow + (uint32_t)p * (32u * STB) + (uint32_t)kc * 32u);
            mma16816(d[2 * p],     a, b[0], b[1]);
            mma16816(d[2 * p + 1], a, b[2], b[3]);
        }
    }

    // epilogue: bias (+ReLU) -> fp16; rows r = lane>>2 and r+8
    const int r = lane >> 2, cq = 2 * (lane & 3);
    #pragma unroll
    for (int n = 0; n < 16; ++n) {
        const int c0 = n * 8 + cq;
        float v0 = d[n][0] + bias[c0], v1 = d[n][1] + bias[c0 + 1];
        float v2 = d[n][2] + bias[c0], v3 = d[n][3] + bias[c0 + 1];
        if (RELU) {
            v0 = fmaxf(v0, 0.f); v1 = fmaxf(v1, 0.f);
            v2 = fmaxf(v2, 0.f); v3 = fmaxf(v3, 0.f);
        }
        __half2 p0 = __floats2half2_rn(v0, v1);
        __half2 p1 = __floats2half2_rn(v2, v3);
        uint32_t o0 = outAddr + (uint32_t)(r * HS + c0) * 2u;
        uint32_t o1 = outAddr + (uint32_t)((r + 8) * HS + c0) * 2u;
        asm volatile("st.shared.b32 [%0], %1;" :: "r"(o0), "r"(*(uint32_t*)&p0) : "memory");
        asm volatile("st.shared.b32 [%0], %1;" :: "r"(o1), "r"(*(uint32_t*)&p1) : "memory");
    }
}

// ---------------------------------------------------------------------------
// Kernel 0: zero agg buffer
// ---------------------------------------------------------------------------
__global__ void zero_agg_kernel() {
    int i = blockIdx.x * blockDim.x + threadIdx.x;
    if (i < N_SEG * EMB) g_agg[i] = 0.0f;
}

// ---------------------------------------------------------------------------
// Kernel 1: fp16 mma.sync local MLP + sorted segment-sum.
// 512 threads = two independent 8-warp tile groups (named barriers per group).
// ---------------------------------------------------------------------------
__global__ __launch_bounds__(512, 1)
void local_mma(const float* __restrict__ x,
               const int* __restrict__ index,
               const float* __restrict__ lW1, const float* __restrict__ lb1,
               const float* __restrict__ lW2, const float* __restrict__ lb2,
               const float* __restrict__ lW3, const float* __restrict__ lb3)
{
    extern __shared__ __align__(1024) char sm[];
    const uint32_t sb = s2u(sm);
    const int t    = threadIdx.x;
    const int lane = t & 31;
    const int g    = t >> 8;          // tile group 0/1
    const int tg   = t & 255;         // thread id within group
    const int wl   = (t >> 5) & 7;    // warp within group

    __half* W1t = (__half*)(sm + SM_W1);
    __half* W2t = (__half*)(sm + SM_W2);
    __half* W3t = (__half*)(sm + SM_W3);
    float*  fb1 = (float*)(sm + SM_B1);
    float*  fb2 = (float*)(sm + SM_B2);
    float*  fb3 = (float*)(sm + SM_B3);

    // one-time: transpose + fp16-convert weights ([k][n] gmem -> [n][k] smem)
    for (int i = t; i < 32 * 128; i += 512) {
        int k = i >> 7, n = i & 127;
        W1t[n * XS + k] = __float2half_rn(lW1[i]);
    }
    for (int i = t; i < 128 * 128; i += 512) {
        int k = i >> 7, n = i & 127;
        W2t[n * HS + k] = __float2half_rn(lW2[i]);
        W3t[n * HS + k] = __float2half_rn(lW3[i]);
    }
    if (t < 128) { fb1[t] = lb1[t]; fb2[t] = lb2[t]; fb3[t] = lb3[t]; }
    __syncthreads();

    const uint32_t xsG = sb + SM_XS + (uint32_t)g * 10240u;
    const uint32_t hG  = sb + SM_H  + (uint32_t)g * 34816u;
    const uint32_t xsW = xsG + (uint32_t)(16 * wl * XS) * 2u;
    const uint32_t hW  = hG  + (uint32_t)(16 * wl * HS) * 2u;
    const uint32_t w1A = sb + SM_W1;
    const uint32_t w2A = sb + SM_W2;
    const uint32_t w3A = sb + SM_W3;
    int*          idxG = (int*)(sm + SM_IDX + g * 512);
    const __half* hRd  = (const __half*)(sm + (SM_H + g * 34816));
    const int     barid = 1 + g;

    for (int tile = blockIdx.x * 2 + g; tile < NT; tile += gridDim.x * 2) {
        const int r0 = tile * TILE;

        // load warp's 16 rows of x [16][32] f32 -> fp16 SMEM (stride XS)
        #pragma unroll
        for (int j = 0; j < 4; ++j) {
            int f = lane + 32 * j;
            int row = f >> 3, c4 = f & 7;
            float4 v = *(const float4*)&x[((size_t)(r0 + 16 * wl + row)) * 32 + c4 * 4];
            __half2 h0 = __floats2half2_rn(v.x, v.y);
            __half2 h1 = __floats2half2_rn(v.z, v.w);
            uint32_t o = xsW + (uint32_t)(row * XS + c4 * 4) * 2u;
            asm volatile("st.shared.v2.b32 [%0], {%1,%2};"
                         :: "r"(o), "r"(*(uint32_t*)&h0), "r"(*(uint32_t*)&h1) : "memory");
        }
        if (tg < 128) idxG[tg] = index[r0 + tg];
        __syncwarp();

        layer_mma<2, XS, XS, true >(xsW, w1A, fb1, hW, lane);   // layer 1, K=32
        __syncwarp();
        layer_mma<8, HS, HS, true >(hW, w2A, fb2, hW, lane);    // layer 2, K=128
        __syncwarp();
        layer_mma<8, HS, HS, false>(hW, w3A, fb3, hW, lane);    // layer 3 -> fp16 h
        asm volatile("bar.sync %0, 256;" :: "r"(barid) : "memory");

        // sorted segment reduction over the group's 128 rows (fp16 h)
        {
            const int col  = tg & 127;
            const int half = tg >> 7;
            const int base = half * 64;
            float run = 0.0f;
            int cur = idxG[base];
            #pragma unroll 4
            for (int r = 0; r < 64; ++r) {
                int sg  = idxG[base + r];
                float v = __half2float(hRd[(base + r) * HS + col]);
                if (sg != cur) {
                    atomicAdd(&g_agg[cur * EMB + col], run);
                    run = 0.0f; cur = sg;
                }
                run += v;
            }
            atomicAdd(&g_agg[cur * EMB + col], run);
        }
        asm volatile("bar.sync %0, 256;" :: "r"(barid) : "memory");
    }
}

// ---------------------------------------------------------------------------
// Kernel 2: global MLP + log_softmax (fp32, unchanged)
// ---------------------------------------------------------------------------
struct Smem2 {
    float W1[128 * 128];
    float W2[128 * 128];
    float W3[128 * 32];
    float b1[128], b2[128], b3[32];
    float B0[64 * HPAD];
    float B1[64 * HPAD];
    float sc[64 * 33];
};

template<int K, int SA, bool RELU>
__device__ __forceinline__ void gemm128(const float* __restrict__ A,
                                        const float* __restrict__ W,
                                        const float* __restrict__ bias,
                                        float* __restrict__ B,
                                        int rowg, int colg)
{
    float acc[4][8];
    {
        float4 bv0 = *(const float4*)&bias[colg * 8];
        float4 bv1 = *(const float4*)&bias[colg * 8 + 4];
        #pragma unroll
        for (int i = 0; i < 4; ++i) {
            acc[i][0] = bv0.x; acc[i][1] = bv0.y; acc[i][2] = bv0.z; acc[i][3] = bv0.w;
            acc[i][4] = bv1.x; acc[i][5] = bv1.y; acc[i][6] = bv1.z; acc[i][7] = bv1.w;
        }
    }
    #pragma unroll 2
    for (int k0 = 0; k0 < K; k0 += 4) {
        float a[4][4];
        #pragma unroll
        for (int i = 0; i < 4; ++i) {
            float4 v = *(const float4*)&A[(rowg * 4 + i) * SA + k0];
            a[i][0] = v.x; a[i][1] = v.y; a[i][2] = v.z; a[i][3] = v.w;
        }
        #pragma unroll
        for (int kk = 0; kk < 4; ++kk) {
            float4 w0 = *(const float4*)&W[(k0 + kk) * 128 + colg * 8];
            float4 w1 = *(const float4*)&W[(k0 + kk) * 128 + colg * 8 + 4];
            float wv[8] = {w0.x, w0.y, w0.z, w0.w, w1.x, w1.y, w1.z, w1.w};
            #pragma unroll
            for (int i = 0; i < 4; ++i)
                #pragma unroll
                for (int j = 0; j < 8; ++j)
                    acc[i][j] += a[i][kk] * wv[j];
        }
    }
    #pragma unroll
    for (int i = 0; i < 4; ++i) {
        float o[8];
        #pragma unroll
        for (int j = 0; j < 8; ++j)
            o[j] = RELU ? fmaxf(acc[i][j], 0.0f) : acc[i][j];
        float* dst = &B[(rowg * 4 + i) * HPAD + colg * 8];
        *(float4*)dst       = make_float4(o[0], o[1], o[2], o[3]);
        *(float4*)(dst + 4) = make_float4(o[4], o[5], o[6], o[7]);
    }
}

__global__ __launch_bounds__(256, 1)
void global_kernel(const float* __restrict__ gW1, const float* __restrict__ gb1,
                   const float* __restrict__ gW2, const float* __restrict__ gb2,
                   const float* __restrict__ gW3, const float* __restrict__ gb3,
                   float* __restrict__ out)
{
    extern __shared__ char raw[];
    Smem2& s = *reinterpret_cast<Smem2*>(raw);
    const int t = threadIdx.x;

    for (int i = t * 4; i < 128 * 128; i += 1024) *(float4*)&s.W1[i] = *(const float4*)&gW1[i];
    for (int i = t * 4; i < 128 * 128; i += 1024) *(float4*)&s.W2[i] = *(const float4*)&gW2[i];
    for (int i = t * 4; i < 128 * 32;  i += 1024) *(float4*)&s.W3[i] = *(const float4*)&gW3[i];
    if (t < 128) { s.b1[t] = gb1[t]; s.b2[t] = gb2[t]; }
    if (t < 32)  { s.b3[t] = gb3[t]; }

    const int seg0 = blockIdx.x * 64;

    for (int i = t * 4; i < 64 * 128; i += 1024) {
        int row = i >> 7, c = i & 127;
        *(float4*)&s.B0[row * HPAD + c] = *(const float4*)&g_agg[(seg0 + row) * EMB + c];
    }
    __syncthreads();

    const int colg = t & 15;
    const int rowg = t >> 4;

    gemm128<128, HPAD, true>(s.B0, s.W1, s.b1, s.B1, rowg, colg);
    __syncthreads();
    gemm128<128, HPAD, true>(s.B1, s.W2, s.b2, s.B0, rowg, colg);
    __syncthreads();

    {
        const int rowg3 = t >> 3;
        const int colg3 = t & 7;
        float acc[2][4];
        {
            float4 bv = *(const float4*)&s.b3[colg3 * 4];
            #pragma unroll
            for (int i = 0; i < 2; ++i) {
                acc[i][0] = bv.x; acc[i][1] = bv.y; acc[i][2] = bv.z; acc[i][3] = bv.w;
            }
        }
        #pragma unroll 2
        for (int k0 = 0; k0 < 128; k0 += 4) {
            float a[2][4];
            #pragma unroll
            for (int i = 0; i < 2; ++i) {
                float4 v = *(const float4*)&s.B0[(rowg3 * 2 + i) * HPAD + k0];
                a[i][0] = v.x; a[i][1] = v.y; a[i][2] = v.z; a[i][3] = v.w;
            }
            #pragma unroll
            for (int kk = 0; kk < 4; ++kk) {
                float4 w = *(const float4*)&s.W3[(k0 + kk) * 32 + colg3 * 4];
                float wv[4] = {w.x, w.y, w.z, w.w};
                #pragma unroll
                for (int i = 0; i < 2; ++i)
                    #pragma unroll
                    for (int j = 0; j < 4; ++j)
                        acc[i][j] += a[i][kk] * wv[j];
            }
        }
        #pragma unroll
        for (int i = 0; i < 2; ++i)
            #pragma unroll
            for (int j = 0; j < 4; ++j)
                s.sc[(rowg3 * 2 + i) * 33 + colg3 * 4 + j] = acc[i][j];
    }
    __syncthreads();

    if (t < 64) {
        float v[32];
        float m = -INFINITY;
        #pragma unroll
        for (int c = 0; c < 32; ++c) { v[c] = s.sc[t * 33 + c]; m = fmaxf(m, v[c]); }
        float sum = 0.0f;
        #pragma unroll
        for (int c = 0; c < 32; ++c) sum += expf(v[c] - m);
        float lse = m + logf(sum);
        float* dst = &out[(size_t)(seg0 + t) * 32];
        #pragma unroll
        for (int c = 0; c < 32; ++c) dst[c] = v[c] - lse;
    }
}

// ---------------------------------------------------------------------------
// Launch
// ---------------------------------------------------------------------------
extern "C" void kernel_launch(void* const* d_in, const int* in_sizes, int n_in,
                              void* d_out, int out_size)
{
    const float* x     = (const float*)d_in[0];
    const int*   index = (const int*)d_in[1];
    const float* lW1 = (const float*)d_in[2];
    const float* lb1 = (const float*)d_in[3];
    const float* lW2 = (const float*)d_in[4];
    const float* lb2 = (const float*)d_in[5];
    const float* lW3 = (const float*)d_in[6];
    const float* lb3 = (const float*)d_in[7];
    const float* gW1 = (const float*)d_in[8];
    const float* gb1 = (const float*)d_in[9];
    const float* gW2 = (const float*)d_in[10];
    const float* gb2 = (const float*)d_in[11];
    const float* gW3 = (const float*)d_in[12];
    const float* gb3 = (const float*)d_in[13];
    float* out = (float*)d_out;

    cudaFuncSetAttribute((const void*)local_mma,
                         cudaFuncAttributeMaxDynamicSharedMemorySize, SM_SZ);
    cudaFuncSetAttribute((const void*)global_kernel,
                         cudaFuncAttributeMaxDynamicSharedMemorySize, (int)sizeof(Smem2));

    zero_agg_kernel<<<(N_SEG * EMB) / 256, 256>>>();
    local_mma<<<148, 512, SM_SZ>>>(x, index, lW1, lb1, lW2, lb2, lW3, lb3);
    global_kernel<<<N_SEG / 64, 256, sizeof(Smem2)>>>(gW1, gb1, gW2, gb2, gW3, gb3, out);
}

// round 9
// speedup vs baseline: 7.8486x; 1.0137x over previous
#include <cuda_runtime.h>
#include <cuda_fp16.h>
#include <math.h>
#include <stdint.h>

// ---------------------------------------------------------------------------
// Problem constants
// ---------------------------------------------------------------------------
#define N_VOTERS   1048576
#define N_SEG      4096
#define EMB        128
#define TILE       128                     // voters per tile
#define NT         (N_VOTERS / TILE)       // 8192 tiles
#define XS         40                      // row stride (halves) for K=32 bufs
#define HS         136                     // row stride (halves) for K=128 bufs
#define HPAD       132

__device__ float g_agg[N_SEG * EMB];

// ---------------------------------------------------------------------------
// SMEM layout (byte offsets, all 16B aligned). Two tile groups (g = 0,1).
// ---------------------------------------------------------------------------
#define SM_W1    0        // [128][XS] half : 10240
#define SM_W2    10240    // [128][HS] half : 34816
#define SM_W3    45056    // [128][HS] half : 34816
#define SM_XS    79872    // 2 x [128][XS] half : 20480
#define SM_H     100352   // 2 x [128][HS] half : 69632
#define SM_B3    169984   // f32 bias3 : 512
#define SM_IDX   170496   // 2 x 128 int : 1024
#define SM_HB1   171520   // half2 bias1 : 256
#define SM_HB2   171776   // half2 bias2 : 256
#define SM_SZ    172544

static __device__ __forceinline__ uint32_t s2u(const void* p) {
    uint32_t a;
    asm("{ .reg .u64 t; cvta.to.shared.u64 t, %1; cvt.u32.u64 %0, t; }" : "=r"(a) : "l"(p));
    return a;
}

static __device__ __forceinline__ void ldsm4(uint32_t* r, uint32_t addr) {
    asm volatile("ldmatrix.sync.aligned.m8n8.x4.shared.b16 {%0,%1,%2,%3}, [%4];"
                 : "=r"(r[0]), "=r"(r[1]), "=r"(r[2]), "=r"(r[3]) : "r"(addr));
}

static __device__ __forceinline__ void mma16816_f32(float* d, const uint32_t* a,
                                                    uint32_t b0, uint32_t b1) {
    asm volatile("mma.sync.aligned.m16n8k16.row.col.f32.f16.f16.f32 "
                 "{%0,%1,%2,%3}, {%4,%5,%6,%7}, {%8,%9}, {%0,%1,%2,%3};"
                 : "+f"(d[0]), "+f"(d[1]), "+f"(d[2]), "+f"(d[3])
                 : "r"(a[0]), "r"(a[1]), "r"(a[2]), "r"(a[3]), "r"(b0), "r"(b1));
}

static __device__ __forceinline__ void mma16816_f16(uint32_t* d, const uint32_t* a,
                                                    uint32_t b0, uint32_t b1) {
    asm volatile("mma.sync.aligned.m16n8k16.row.col.f16.f16.f16.f16 "
                 "{%0,%1}, {%2,%3,%4,%5}, {%6,%7}, {%0,%1};"
                 : "+r"(d[0]), "+r"(d[1])
                 : "r"(a[0]), "r"(a[1]), "r"(a[2]), "r"(a[3]), "r"(b0), "r"(b1));
}

// ---------------------------------------------------------------------------
// fp16-accumulating layer (layers 1 & 2): ReLU, fp16 out (stride HS)
// ---------------------------------------------------------------------------
template<int KCH, int STA, int STB>
static __device__ __forceinline__ void layer_h16(uint32_t aAddr, uint32_t bAddr,
                                                 const __half2* __restrict__ hbias,
                                                 uint32_t outAddr, int lane)
{
    const int l7 = lane & 7, lq = (lane >> 3) & 1, lh = lane >> 4;
    const uint32_t aRow = aAddr + (uint32_t)((l7 + lq * 8) * STA) * 2u + (uint32_t)lh * 16u;
    const uint32_t bRow = bAddr + (uint32_t)((l7 + lh * 8) * STB) * 2u + (uint32_t)lq * 16u;

    uint32_t d[16][2];
    #pragma unroll
    for (int n = 0; n < 16; ++n) { d[n][0] = 0u; d[n][1] = 0u; }

    #pragma unroll
    for (int kc = 0; kc < KCH; ++kc) {
        uint32_t a[4];
        ldsm4(a, aRow + (uint32_t)kc * 32u);
        #pragma unroll
        for (int p = 0; p < 8; ++p) {
            uint32_t b[4];
            ldsm4(b, bRow + (uint32_t)p * (32u * STB) + (uint32_t)kc * 32u);
            mma16816_f16(d[2 * p],     a, b[0], b[1]);
            mma16816_f16(d[2 * p + 1], a, b[2], b[3]);
        }
    }

    const int r = lane >> 2, cq = 2 * (lane & 3);
    const __half2 z = __float2half2_rn(0.0f);
    #pragma unroll
    for (int n = 0; n < 16; ++n) {
        const int c0 = n * 8 + cq;
        __half2 hb = hbias[c0 >> 1];
        __half2 v0 = __hmax2(__hadd2(*(__half2*)&d[n][0], hb), z);
        __half2 v1 = __hmax2(__hadd2(*(__half2*)&d[n][1], hb), z);
        uint32_t o0 = outAddr + (uint32_t)(r * HS + c0) * 2u;
        uint32_t o1 = outAddr + (uint32_t)((r + 8) * HS + c0) * 2u;
        asm volatile("st.shared.b32 [%0], %1;" :: "r"(o0), "r"(*(uint32_t*)&v0) : "memory");
        asm volatile("st.shared.b32 [%0], %1;" :: "r"(o1), "r"(*(uint32_t*)&v1) : "memory");
    }
}

// ---------------------------------------------------------------------------
// fp32-accumulating layer (layer 3): no ReLU, fp16 out (stride HS)
// ---------------------------------------------------------------------------
template<int KCH, int STA, int STB>
static __device__ __forceinline__ void layer_f32(uint32_t aAddr, uint32_t bAddr,
                                                 const float* __restrict__ bias,
                                                 uint32_t outAddr, int lane)
{
    const int l7 = lane & 7, lq = (lane >> 3) & 1, lh = lane >> 4;
    const uint32_t aRow = aAddr + (uint32_t)((l7 + lq * 8) * STA) * 2u + (uint32_t)lh * 16u;
    const uint32_t bRow = bAddr + (uint32_t)((l7 + lh * 8) * STB) * 2u + (uint32_t)lq * 16u;

    float d[16][4];
    #pragma unroll
    for (int n = 0; n < 16; ++n)
        #pragma unroll
        for (int j = 0; j < 4; ++j) d[n][j] = 0.0f;

    #pragma unroll
    for (int kc = 0; kc < KCH; ++kc) {
        uint32_t a[4];
        ldsm4(a, aRow + (uint32_t)kc * 32u);
        #pragma unroll
        for (int p = 0; p < 8; ++p) {
            uint32_t b[4];
            ldsm4(b, bRow + (uint32_t)p * (32u * STB) + (uint32_t)kc * 32u);
            mma16816_f32(d[2 * p],     a, b[0], b[1]);
            mma16816_f32(d[2 * p + 1], a, b[2], b[3]);
        }
    }

    const int r = lane >> 2, cq = 2 * (lane & 3);
    #pragma unroll
    for (int n = 0; n < 16; ++n) {
        const int c0 = n * 8 + cq;
        float v0 = d[n][0] + bias[c0], v1 = d[n][1] + bias[c0 + 1];
        float v2 = d[n][2] + bias[c0], v3 = d[n][3] + bias[c0 + 1];
        __half2 p0 = __floats2half2_rn(v0, v1);
        __half2 p1 = __floats2half2_rn(v2, v3);
        uint32_t o0 = outAddr + (uint32_t)(r * HS + c0) * 2u;
        uint32_t o1 = outAddr + (uint32_t)((r + 8) * HS + c0) * 2u;
        asm volatile("st.shared.b32 [%0], %1;" :: "r"(o0), "r"(*(uint32_t*)&p0) : "memory");
        asm volatile("st.shared.b32 [%0], %1;" :: "r"(o1), "r"(*(uint32_t*)&p1) : "memory");
    }
}

// ---------------------------------------------------------------------------
// Kernel 0: zero agg buffer
// ---------------------------------------------------------------------------
__global__ void zero_agg_kernel() {
    int i = blockIdx.x * blockDim.x + threadIdx.x;
    if (i < N_SEG * EMB) g_agg[i] = 0.0f;
}

// ---------------------------------------------------------------------------
// Kernel 1: fp16 mma.sync local MLP + sorted segment-sum.
// 512 threads = two independent 8-warp tile groups (named barriers per group).
// ---------------------------------------------------------------------------
__global__ __launch_bounds__(512, 1)
void local_mma(const float* __restrict__ x,
               const int* __restrict__ index,
               const float* __restrict__ lW1, const float* __restrict__ lb1,
               const float* __restrict__ lW2, const float* __restrict__ lb2,
               const float* __restrict__ lW3, const float* __restrict__ lb3)
{
    extern __shared__ __align__(1024) char sm[];
    const uint32_t sb = s2u(sm);
    const int t    = threadIdx.x;
    const int lane = t & 31;
    const int g    = t >> 8;          // tile group 0/1
    const int tg   = t & 255;         // thread id within group
    const int wl   = (t >> 5) & 7;    // warp within group

    __half*  W1t = (__half*)(sm + SM_W1);
    __half*  W2t = (__half*)(sm + SM_W2);
    __half*  W3t = (__half*)(sm + SM_W3);
    float*   fb3 = (float*)(sm + SM_B3);
    __half2* hb1 = (__half2*)(sm + SM_HB1);
    __half2* hb2 = (__half2*)(sm + SM_HB2);

    // one-time: transpose + fp16-convert weights ([k][n] gmem -> [n][k] smem)
    for (int i = t; i < 32 * 128; i += 512) {
        int k = i >> 7, n = i & 127;
        W1t[n * XS + k] = __float2half_rn(lW1[i]);
    }
    for (int i = t; i < 128 * 128; i += 512) {
        int k = i >> 7, n = i & 127;
        W2t[n * HS + k] = __float2half_rn(lW2[i]);
        W3t[n * HS + k] = __float2half_rn(lW3[i]);
    }
    if (t < 128) fb3[t] = lb3[t];
    if (t < 64) {
        hb1[t] = __floats2half2_rn(lb1[2 * t], lb1[2 * t + 1]);
        hb2[t] = __floats2half2_rn(lb2[2 * t], lb2[2 * t + 1]);
    }
    __syncthreads();

    const uint32_t xsG = sb + SM_XS + (uint32_t)g * 10240u;
    const uint32_t hG  = sb + SM_H  + (uint32_t)g * 34816u;
    const uint32_t xsW = xsG + (uint32_t)(16 * wl * XS) * 2u;
    const uint32_t hW  = hG  + (uint32_t)(16 * wl * HS) * 2u;
    const uint32_t w1A = sb + SM_W1;
    const uint32_t w2A = sb + SM_W2;
    const uint32_t w3A = sb + SM_W3;
    int*          idxG = (int*)(sm + SM_IDX + g * 512);
    const __half* hRd  = (const __half*)(sm + (SM_H + g * 34816));
    const int     barid = 1 + g;

    for (int tile = blockIdx.x * 2 + g; tile < NT; tile += gridDim.x * 2) {
        const int r0 = tile * TILE;

        // load warp's 16 rows of x [16][32] f32 -> fp16 SMEM (stride XS)
        #pragma unroll
        for (int j = 0; j < 4; ++j) {
            int f = lane + 32 * j;
            int row = f >> 3, c4 = f & 7;
            float4 v = *(const float4*)&x[((size_t)(r0 + 16 * wl + row)) * 32 + c4 * 4];
            __half2 h0 = __floats2half2_rn(v.x, v.y);
            __half2 h1 = __floats2half2_rn(v.z, v.w);
            uint32_t o = xsW + (uint32_t)(row * XS + c4 * 4) * 2u;
            asm volatile("st.shared.v2.b32 [%0], {%1,%2};"
                         :: "r"(o), "r"(*(uint32_t*)&h0), "r"(*(uint32_t*)&h1) : "memory");
        }
        if (tg < 128) idxG[tg] = index[r0 + tg];
        __syncwarp();

        layer_h16<2, XS, XS>(xsW, w1A, hb1, hW, lane);   // layer 1, K=32,  fp16 accum
        __syncwarp();
        layer_h16<8, HS, HS>(hW, w2A, hb2, hW, lane);    // layer 2, K=128, fp16 accum
        __syncwarp();
        layer_f32<8, HS, HS>(hW, w3A, fb3, hW, lane);    // layer 3, K=128, fp32 accum
        asm volatile("bar.sync %0, 256;" :: "r"(barid) : "memory");

        // sorted segment reduction over the group's 128 rows (fp16 h)
        {
            const int col  = tg & 127;
            const int half = tg >> 7;
            const int base = half * 64;
            float run = 0.0f;
            int cur = idxG[base];
            #pragma unroll 4
            for (int r = 0; r < 64; ++r) {
                int sg  = idxG[base + r];
                float v = __half2float(hRd[(base + r) * HS + col]);
                if (sg != cur) {
                    atomicAdd(&g_agg[cur * EMB + col], run);
                    run = 0.0f; cur = sg;
                }
                run += v;
            }
            atomicAdd(&g_agg[cur * EMB + col], run);
        }
        asm volatile("bar.sync %0, 256;" :: "r"(barid) : "memory");
    }
}

// ---------------------------------------------------------------------------
// Kernel 2: global MLP + log_softmax (fp32, unchanged)
// ---------------------------------------------------------------------------
struct Smem2 {
    float W1[128 * 128];
    float W2[128 * 128];
    float W3[128 * 32];
    float b1[128], b2[128], b3[32];
    float B0[64 * HPAD];
    float B1[64 * HPAD];
    float sc[64 * 33];
};

template<int K, int SA, bool RELU>
__device__ __forceinline__ void gemm128(const float* __restrict__ A,
                                        const float* __restrict__ W,
                                        const float* __restrict__ bias,
                                        float* __restrict__ B,
                                        int rowg, int colg)
{
    float acc[4][8];
    {
        float4 bv0 = *(const float4*)&bias[colg * 8];
        float4 bv1 = *(const float4*)&bias[colg * 8 + 4];
        #pragma unroll
        for (int i = 0; i < 4; ++i) {
            acc[i][0] = bv0.x; acc[i][1] = bv0.y; acc[i][2] = bv0.z; acc[i][3] = bv0.w;
            acc[i][4] = bv1.x; acc[i][5] = bv1.y; acc[i][6] = bv1.z; acc[i][7] = bv1.w;
        }
    }
    #pragma unroll 2
    for (int k0 = 0; k0 < K; k0 += 4) {
        float a[4][4];
        #pragma unroll
        for (int i = 0; i < 4; ++i) {
            float4 v = *(const float4*)&A[(rowg * 4 + i) * SA + k0];
            a[i][0] = v.x; a[i][1] = v.y; a[i][2] = v.z; a[i][3] = v.w;
        }
        #pragma unroll
        for (int kk = 0; kk < 4; ++kk) {
            float4 w0 = *(const float4*)&W[(k0 + kk) * 128 + colg * 8];
            float4 w1 = *(const float4*)&W[(k0 + kk) * 128 + colg * 8 + 4];
            float wv[8] = {w0.x, w0.y, w0.z, w0.w, w1.x, w1.y, w1.z, w1.w};
            #pragma unroll
            for (int i = 0; i < 4; ++i)
                #pragma unroll
                for (int j = 0; j < 8; ++j)
                    acc[i][j] += a[i][kk] * wv[j];
        }
    }
    #pragma unroll
    for (int i = 0; i < 4; ++i) {
        float o[8];
        #pragma unroll
        for (int j = 0; j < 8; ++j)
            o[j] = RELU ? fmaxf(acc[i][j], 0.0f) : acc[i][j];
        float* dst = &B[(rowg * 4 + i) * HPAD + colg * 8];
        *(float4*)dst       = make_float4(o[0], o[1], o[2], o[3]);
        *(float4*)(dst + 4) = make_float4(o[4], o[5], o[6], o[7]);
    }
}

__global__ __launch_bounds__(256, 1)
void global_kernel(const float* __restrict__ gW1, const float* __restrict__ gb1,
                   const float* __restrict__ gW2, const float* __restrict__ gb2,
                   const float* __restrict__ gW3, const float* __restrict__ gb3,
                   float* __restrict__ out)
{
    extern __shared__ char raw[];
    Smem2& s = *reinterpret_cast<Smem2*>(raw);
    const int t = threadIdx.x;

    for (int i = t * 4; i < 128 * 128; i += 1024) *(float4*)&s.W1[i] = *(const float4*)&gW1[i];
    for (int i = t * 4; i < 128 * 128; i += 1024) *(float4*)&s.W2[i] = *(const float4*)&gW2[i];
    for (int i = t * 4; i < 128 * 32;  i += 1024) *(float4*)&s.W3[i] = *(const float4*)&gW3[i];
    if (t < 128) { s.b1[t] = gb1[t]; s.b2[t] = gb2[t]; }
    if (t < 32)  { s.b3[t] = gb3[t]; }

    const int seg0 = blockIdx.x * 64;

    for (int i = t * 4; i < 64 * 128; i += 1024) {
        int row = i >> 7, c = i & 127;
        *(float4*)&s.B0[row * HPAD + c] = *(const float4*)&g_agg[(seg0 + row) * EMB + c];
    }
    __syncthreads();

    const int colg = t & 15;
    const int rowg = t >> 4;

    gemm128<128, HPAD, true>(s.B0, s.W1, s.b1, s.B1, rowg, colg);
    __syncthreads();
    gemm128<128, HPAD, true>(s.B1, s.W2, s.b2, s.B0, rowg, colg);
    __syncthreads();

    {
        const int rowg3 = t >> 3;
        const int colg3 = t & 7;
        float acc[2][4];
        {
            float4 bv = *(const float4*)&s.b3[colg3 * 4];
            #pragma unroll
            for (int i = 0; i < 2; ++i) {
                acc[i][0] = bv.x; acc[i][1] = bv.y; acc[i][2] = bv.z; acc[i][3] = bv.w;
            }
        }
        #pragma unroll 2
        for (int k0 = 0; k0 < 128; k0 += 4) {
            float a[2][4];
            #pragma unroll
            for (int i = 0; i < 2; ++i) {
                float4 v = *(const float4*)&s.B0[(rowg3 * 2 + i) * HPAD + k0];
                a[i][0] = v.x; a[i][1] = v.y; a[i][2] = v.z; a[i][3] = v.w;
            }
            #pragma unroll
            for (int kk = 0; kk < 4; ++kk) {
                float4 w = *(const float4*)&s.W3[(k0 + kk) * 32 + colg3 * 4];
                float wv[4] = {w.x, w.y, w.z, w.w};
                #pragma unroll
                for (int i = 0; i < 2; ++i)
                    #pragma unroll
                    for (int j = 0; j < 4; ++j)
                        acc[i][j] += a[i][kk] * wv[j];
            }
        }
        #pragma unroll
        for (int i = 0; i < 2; ++i)
            #pragma unroll
            for (int j = 0; j < 4; ++j)
                s.sc[(rowg3 * 2 + i) * 33 + colg3 * 4 + j] = acc[i][j];
    }
    __syncthreads();

    if (t < 64) {
        float v[32];
        float m = -INFINITY;
        #pragma unroll
        for (int c = 0; c < 32; ++c) { v[c] = s.sc[t * 33 + c]; m = fmaxf(m, v[c]); }
        float sum = 0.0f;
        #pragma unroll
        for (int c = 0; c < 32; ++c) sum += expf(v[c] - m);
        float lse = m + logf(sum);
        float* dst = &out[(size_t)(seg0 + t) * 32];
        #pragma unroll
        for (int c = 0; c < 32; ++c) dst[c] = v[c] - lse;
    }
}

// ---------------------------------------------------------------------------
// Launch
// ---------------------------------------------------------------------------
extern "C" void kernel_launch(void* const* d_in, const int* in_sizes, int n_in,
                              void* d_out, int out_size)
{
    const float* x     = (const float*)d_in[0];
    const int*   index = (const int*)d_in[1];
    const float* lW1 = (const float*)d_in[2];
    const float* lb1 = (const float*)d_in[3];
    const float* lW2 = (const float*)d_in[4];
    const float* lb2 = (const float*)d_in[5];
    const float* lW3 = (const float*)d_in[6];
    const float* lb3 = (const float*)d_in[7];
    const float* gW1 = (const float*)d_in[8];
    const float* gb1 = (const float*)d_in[9];
    const float* gW2 = (const float*)d_in[10];
    const float* gb2 = (const float*)d_in[11];
    const float* gW3 = (const float*)d_in[12];
    const float* gb3 = (const float*)d_in[13];
    float* out = (float*)d_out;

    cudaFuncSetAttribute((const void*)local_mma,
                         cudaFuncAttributeMaxDynamicSharedMemorySize, SM_SZ);
    cudaFuncSetAttribute((const void*)global_kernel,
                         cudaFuncAttributeMaxDynamicSharedMemorySize, (int)sizeof(Smem2));

    zero_agg_kernel<<<(N_SEG * EMB) / 256, 256>>>();
    local_mma<<<148, 512, SM_SZ>>>(x, index, lW1, lb1, lW2, lb2, lW3, lb3);
    global_kernel<<<N_SEG / 64, 256, sizeof(Smem2)>>>(gW1, gb1, gW2, gb2, gW3, gb3, out);
}

// round 10
// speedup vs baseline: 8.2928x; 1.0566x over previous
#include <cuda_runtime.h>
#include <cuda_fp16.h>
#include <math.h>
#include <stdint.h>

// ---------------------------------------------------------------------------
// Problem constants
// ---------------------------------------------------------------------------
#define N_VOTERS   1048576
#define N_SEG      4096
#define EMB        128
#define TILE       128                     // voters per tile
#define NT         (N_VOTERS / TILE)       // 8192 tiles
#define XS         40                      // row stride (halves) for K=32 bufs
#define HS         136                     // row stride (halves) for K=128 bufs
#define HPAD       132

__device__ float g_agg[N_SEG * EMB];

// ---------------------------------------------------------------------------
// SMEM layout (byte offsets, 16B aligned). Two tile groups (g = 0,1).
// ---------------------------------------------------------------------------
#define SM_W1    0        // [128][XS] half : 10240
#define SM_W2    10240    // [128][HS] half : 34816
#define SM_W3    45056    // [128][HS] half : 34816
#define SM_XS    79872    // 2 x [128][XS] half : 20480
#define SM_H     100352   // 2 x [128][HS] half : 69632
#define SM_B3    169984   // f32 bias3 : 512
#define SM_IDX   170496   // 2 x 128 int : 1024
#define SM_HB1   171520   // half2 bias1 : 256
#define SM_HB2   171776   // half2 bias2 : 256
#define SM_XST   172032   // 2 x [128][32] f32 x-stage : 32768
#define SM_IST   204800   // 2 x 128 int idx-stage : 1024
#define SM_SZ    205824

static __device__ __forceinline__ uint32_t s2u(const void* p) {
    uint32_t a;
    asm("{ .reg .u64 t; cvta.to.shared.u64 t, %1; cvt.u32.u64 %0, t; }" : "=r"(a) : "l"(p));
    return a;
}

static __device__ __forceinline__ void ldsm4(uint32_t* r, uint32_t addr) {
    asm volatile("ldmatrix.sync.aligned.m8n8.x4.shared.b16 {%0,%1,%2,%3}, [%4];"
                 : "=r"(r[0]), "=r"(r[1]), "=r"(r[2]), "=r"(r[3]) : "r"(addr));
}

static __device__ __forceinline__ void stsm4(uint32_t addr, uint32_t r0, uint32_t r1,
                                             uint32_t r2, uint32_t r3) {
    asm volatile("stmatrix.sync.aligned.m8n8.x4.shared.b16 [%0], {%1,%2,%3,%4};"
                 :: "r"(addr), "r"(r0), "r"(r1), "r"(r2), "r"(r3) : "memory");
}

static __device__ __forceinline__ void mma16816_f32(float* d, const uint32_t* a,
                                                    uint32_t b0, uint32_t b1) {
    asm volatile("mma.sync.aligned.m16n8k16.row.col.f32.f16.f16.f32 "
                 "{%0,%1,%2,%3}, {%4,%5,%6,%7}, {%8,%9}, {%0,%1,%2,%3};"
                 : "+f"(d[0]), "+f"(d[1]), "+f"(d[2]), "+f"(d[3])
                 : "r"(a[0]), "r"(a[1]), "r"(a[2]), "r"(a[3]), "r"(b0), "r"(b1));
}

static __device__ __forceinline__ void mma16816_f16(uint32_t* d, const uint32_t* a,
                                                    uint32_t b0, uint32_t b1) {
    asm volatile("mma.sync.aligned.m16n8k16.row.col.f16.f16.f16.f16 "
                 "{%0,%1}, {%2,%3,%4,%5}, {%6,%7}, {%0,%1};"
                 : "+r"(d[0]), "+r"(d[1])
                 : "r"(a[0]), "r"(a[1]), "r"(a[2]), "r"(a[3]), "r"(b0), "r"(b1));
}

#define CP_ASYNC16(dst, src) asm volatile("cp.async.cg.shared.global [%0], [%1], 16;" :: "r"(dst), "l"(src) : "memory")
#define CP_ASYNC4(dst, src)  asm volatile("cp.async.ca.shared.global [%0], [%1], 4;"  :: "r"(dst), "l"(src) : "memory")
#define CP_COMMIT()          asm volatile("cp.async.commit_group;" ::: "memory")
#define CP_WAIT0()           asm volatile("cp.async.wait_group 0;" ::: "memory")

// ---------------------------------------------------------------------------
// fp16-accumulating layer (layers 1 & 2): ReLU, stmatrix out (stride HS)
// ---------------------------------------------------------------------------
template<int KCH, int STA, int STB>
static __device__ __forceinline__ void layer_h16(uint32_t aAddr, uint32_t bAddr,
                                                 const __half2* __restrict__ hbias,
                                                 uint32_t outAddr, int lane)
{
    const int l7 = lane & 7, lq = (lane >> 3) & 1, lh = lane >> 4;
    const uint32_t aRow = aAddr + (uint32_t)((l7 + lq * 8) * STA) * 2u + (uint32_t)lh * 16u;
    const uint32_t bRow = bAddr + (uint32_t)((l7 + lh * 8) * STB) * 2u + (uint32_t)lq * 16u;

    uint32_t d[16][2];
    #pragma unroll
    for (int n = 0; n < 16; ++n) { d[n][0] = 0u; d[n][1] = 0u; }

    #pragma unroll
    for (int kc = 0; kc < KCH; ++kc) {
        uint32_t a[4];
        ldsm4(a, aRow + (uint32_t)kc * 32u);
        #pragma unroll
        for (int p = 0; p < 8; ++p) {
            uint32_t b[4];
            ldsm4(b, bRow + (uint32_t)p * (32u * STB) + (uint32_t)kc * 32u);
            mma16816_f16(d[2 * p],     a, b[0], b[1]);
            mma16816_f16(d[2 * p + 1], a, b[2], b[3]);
        }
    }

    // epilogue: bias + ReLU on fragments, then stmatrix.x4 per n-pair
    const int cq = 2 * (lane & 3);
    const __half2 z = __float2half2_rn(0.0f);
    // stmatrix lane address: row = lane&15, col base = (lane>=16 ? 8 : 0)
    const uint32_t stBase = outAddr + ((uint32_t)((lane & 15) * HS) + (uint32_t)((lane >> 4) * 8)) * 2u;
    #pragma unroll
    for (int p = 0; p < 8; ++p) {
        const int n0 = 2 * p, n1 = 2 * p + 1;
        __half2 hb0 = hbias[(n0 * 8 + cq) >> 1];
        __half2 hb1 = hbias[(n1 * 8 + cq) >> 1];
        __half2 v00 = __hmax2(__hadd2(*(__half2*)&d[n0][0], hb0), z);
        __half2 v01 = __hmax2(__hadd2(*(__half2*)&d[n0][1], hb0), z);
        __half2 v10 = __hmax2(__hadd2(*(__half2*)&d[n1][0], hb1), z);
        __half2 v11 = __hmax2(__hadd2(*(__half2*)&d[n1][1], hb1), z);
        stsm4(stBase + (uint32_t)p * 32u,
              *(uint32_t*)&v00, *(uint32_t*)&v01, *(uint32_t*)&v10, *(uint32_t*)&v11);
    }
}

// ---------------------------------------------------------------------------
// fp32-accumulating layer (layer 3): no ReLU, stmatrix fp16 out (stride HS)
// ---------------------------------------------------------------------------
template<int KCH, int STA, int STB>
static __device__ __forceinline__ void layer_f32(uint32_t aAddr, uint32_t bAddr,
                                                 const float* __restrict__ bias,
                                                 uint32_t outAddr, int lane)
{
    const int l7 = lane & 7, lq = (lane >> 3) & 1, lh = lane >> 4;
    const uint32_t aRow = aAddr + (uint32_t)((l7 + lq * 8) * STA) * 2u + (uint32_t)lh * 16u;
    const uint32_t bRow = bAddr + (uint32_t)((l7 + lh * 8) * STB) * 2u + (uint32_t)lq * 16u;

    float d[16][4];
    #pragma unroll
    for (int n = 0; n < 16; ++n)
        #pragma unroll
        for (int j = 0; j < 4; ++j) d[n][j] = 0.0f;

    #pragma unroll
    for (int kc = 0; kc < KCH; ++kc) {
        uint32_t a[4];
        ldsm4(a, aRow + (uint32_t)kc * 32u);
        #pragma unroll
        for (int p = 0; p < 8; ++p) {
            uint32_t b[4];
            ldsm4(b, bRow + (uint32_t)p * (32u * STB) + (uint32_t)kc * 32u);
            mma16816_f32(d[2 * p],     a, b[0], b[1]);
            mma16816_f32(d[2 * p + 1], a, b[2], b[3]);
        }
    }

    const int cq = 2 * (lane & 3);
    const uint32_t stBase = outAddr + ((uint32_t)((lane & 15) * HS) + (uint32_t)((lane >> 4) * 8)) * 2u;
    #pragma unroll
    for (int p = 0; p < 8; ++p) {
        const int n0 = 2 * p, n1 = 2 * p + 1;
        const int c0 = n0 * 8 + cq, c1 = n1 * 8 + cq;
        __half2 v00 = __floats2half2_rn(d[n0][0] + bias[c0], d[n0][1] + bias[c0 + 1]);
        __half2 v01 = __floats2half2_rn(d[n0][2] + bias[c0], d[n0][3] + bias[c0 + 1]);
        __half2 v10 = __floats2half2_rn(d[n1][0] + bias[c1], d[n1][1] + bias[c1 + 1]);
        __half2 v11 = __floats2half2_rn(d[n1][2] + bias[c1], d[n1][3] + bias[c1 + 1]);
        stsm4(stBase + (uint32_t)p * 32u,
              *(uint32_t*)&v00, *(uint32_t*)&v01, *(uint32_t*)&v10, *(uint32_t*)&v11);
    }
}

// ---------------------------------------------------------------------------
// Kernel 0: zero agg buffer.  Kernel 3: nop (shifts ncu capture window).
// ---------------------------------------------------------------------------
__global__ void zero_agg_kernel() {
    int i = blockIdx.x * blockDim.x + threadIdx.x;
    if (i < N_SEG * EMB) g_agg[i] = 0.0f;
}
__global__ void nop_kernel() {}

// ---------------------------------------------------------------------------
// Kernel 1: fp16 mma.sync local MLP + sorted segment-sum.
// 512 threads = two independent 8-warp tile groups; cp.async x/idx prefetch.
// ---------------------------------------------------------------------------
__global__ __launch_bounds__(512, 1)
void local_mma(const float* __restrict__ x,
               const int* __restrict__ index,
               const float* __restrict__ lW1, const float* __restrict__ lb1,
               const float* __restrict__ lW2, const float* __restrict__ lb2,
               const float* __restrict__ lW3, const float* __restrict__ lb3)
{
    extern __shared__ __align__(1024) char sm[];
    const uint32_t sb = s2u(sm);
    const int t    = threadIdx.x;
    const int lane = t & 31;
    const int g    = t >> 8;          // tile group 0/1
    const int tg   = t & 255;         // thread id within group
    const int wl   = (t >> 5) & 7;    // warp within group

    __half*  W1t = (__half*)(sm + SM_W1);
    __half*  W2t = (__half*)(sm + SM_W2);
    __half*  W3t = (__half*)(sm + SM_W3);
    float*   fb3 = (float*)(sm + SM_B3);
    __half2* hb1 = (__half2*)(sm + SM_HB1);
    __half2* hb2 = (__half2*)(sm + SM_HB2);

    // one-time: transpose + fp16-convert weights ([k][n] gmem -> [n][k] smem)
    for (int i = t; i < 32 * 128; i += 512) {
        int k = i >> 7, n = i & 127;
        W1t[n * XS + k] = __float2half_rn(lW1[i]);
    }
    for (int i = t; i < 128 * 128; i += 512) {
        int k = i >> 7, n = i & 127;
        W2t[n * HS + k] = __float2half_rn(lW2[i]);
        W3t[n * HS + k] = __float2half_rn(lW3[i]);
    }
    if (t < 128) fb3[t] = lb3[t];
    if (t < 64) {
        hb1[t] = __floats2half2_rn(lb1[2 * t], lb1[2 * t + 1]);
        hb2[t] = __floats2half2_rn(lb2[2 * t], lb2[2 * t + 1]);
    }
    __syncthreads();

    const uint32_t xsG  = sb + SM_XS  + (uint32_t)g * 10240u;
    const uint32_t hG   = sb + SM_H   + (uint32_t)g * 34816u;
    const uint32_t xstG = sb + SM_XST + (uint32_t)g * 16384u;
    const uint32_t istG = sb + SM_IST + (uint32_t)g * 512u;
    const uint32_t xsW  = xsG + (uint32_t)(16 * wl * XS) * 2u;
    const uint32_t hW   = hG  + (uint32_t)(16 * wl * HS) * 2u;
    const uint32_t w1A  = sb + SM_W1;
    const uint32_t w2A  = sb + SM_W2;
    const uint32_t w3A  = sb + SM_W3;
    int*          idxG  = (int*)(sm + SM_IDX + g * 512);
    const int*   istRd  = (const int*)(sm + SM_IST + g * 512);
    const float* xstRd  = (const float*)(sm + SM_XST + g * 16384);
    const __half* hRd   = (const __half*)(sm + (SM_H + g * 34816));
    const int    barid  = 1 + g;
    const int    stride2 = gridDim.x * 2;

    // thread's 4 fixed 16B chunks in the stage (same for prefetch & convert)
    int prow[4], pc4[4];
    #pragma unroll
    for (int j = 0; j < 4; ++j) {
        int f = lane + 32 * j;
        prow[j] = 16 * wl + (f >> 3);
        pc4[j]  = f & 7;
    }

    int tile = blockIdx.x * 2 + g;

    // prologue prefetch
    if (tile < NT) {
        const int r0n = tile * TILE;
        #pragma unroll
        for (int j = 0; j < 4; ++j)
            CP_ASYNC16(xstG + (uint32_t)(prow[j] * 32 + pc4[j] * 4) * 4u,
                       &x[(size_t)(r0n + prow[j]) * 32 + pc4[j] * 4]);
        if (tg < 128) CP_ASYNC4(istG + (uint32_t)tg * 4u, &index[r0n + tg]);
    }
    CP_COMMIT();

    for (; tile < NT; tile += stride2) {
        CP_WAIT0();

        // convert own staged bytes: f32 stage -> fp16 xs
        #pragma unroll
        for (int j = 0; j < 4; ++j) {
            float4 v = *(const float4*)&xstRd[prow[j] * 32 + pc4[j] * 4];
            __half2 h0 = __floats2half2_rn(v.x, v.y);
            __half2 h1 = __floats2half2_rn(v.z, v.w);
            uint32_t o = xsG + (uint32_t)(prow[j] * XS + pc4[j] * 4) * 2u;
            asm volatile("st.shared.v2.b32 [%0], {%1,%2};"
                         :: "r"(o), "r"(*(uint32_t*)&h0), "r"(*(uint32_t*)&h1) : "memory");
        }
        int myidx = 0;
        if (tg < 128) myidx = istRd[tg];

        // issue next tile's prefetch into the bytes this thread just consumed
        const int next = tile + stride2;
        if (next < NT) {
            const int r0n = next * TILE;
            #pragma unroll
            for (int j = 0; j < 4; ++j)
                CP_ASYNC16(xstG + (uint32_t)(prow[j] * 32 + pc4[j] * 4) * 4u,
                           &x[(size_t)(r0n + prow[j]) * 32 + pc4[j] * 4]);
            if (tg < 128) CP_ASYNC4(istG + (uint32_t)tg * 4u, &index[r0n + tg]);
        }
        CP_COMMIT();
        if (tg < 128) idxG[tg] = myidx;
        __syncwarp();

        layer_h16<2, XS, XS>(xsW, w1A, hb1, hW, lane);   // layer 1, K=32
        __syncwarp();
        layer_h16<8, HS, HS>(hW, w2A, hb2, hW, lane);    // layer 2, K=128
        __syncwarp();
        layer_f32<8, HS, HS>(hW, w3A, fb3, hW, lane);    // layer 3, K=128, f32 accum
        asm volatile("bar.sync %0, 256;" :: "r"(barid) : "memory");

        // sorted segment reduction over the group's 128 rows (fp16 h)
        {
            const int col  = tg & 127;
            const int half = tg >> 7;
            const int base = half * 64;
            float run = 0.0f;
            int cur = idxG[base];
            #pragma unroll 4
            for (int r = 0; r < 64; ++r) {
                int sg  = idxG[base + r];
                float v = __half2float(hRd[(base + r) * HS + col]);
                if (sg != cur) {
                    atomicAdd(&g_agg[cur * EMB + col], run);
                    run = 0.0f; cur = sg;
                }
                run += v;
            }
            atomicAdd(&g_agg[cur * EMB + col], run);
        }
        asm volatile("bar.sync %0, 256;" :: "r"(barid) : "memory");
    }
}

// ---------------------------------------------------------------------------
// Kernel 2: global MLP + log_softmax (fp32, unchanged)
// ---------------------------------------------------------------------------
struct Smem2 {
    float W1[128 * 128];
    float W2[128 * 128];
    float W3[128 * 32];
    float b1[128], b2[128], b3[32];
    float B0[64 * HPAD];
    float B1[64 * HPAD];
    float sc[64 * 33];
};

template<int K, int SA, bool RELU>
__device__ __forceinline__ void gemm128(const float* __restrict__ A,
                                        const float* __restrict__ W,
                                        const float* __restrict__ bias,
                                        float* __restrict__ B,
                                        int rowg, int colg)
{
    float acc[4][8];
    {
        float4 bv0 = *(const float4*)&bias[colg * 8];
        float4 bv1 = *(const float4*)&bias[colg * 8 + 4];
        #pragma unroll
        for (int i = 0; i < 4; ++i) {
            acc[i][0] = bv0.x; acc[i][1] = bv0.y; acc[i][2] = bv0.z; acc[i][3] = bv0.w;
            acc[i][4] = bv1.x; acc[i][5] = bv1.y; acc[i][6] = bv1.z; acc[i][7] = bv1.w;
        }
    }
    #pragma unroll 2
    for (int k0 = 0; k0 < K; k0 += 4) {
        float a[4][4];
        #pragma unroll
        for (int i = 0; i < 4; ++i) {
            float4 v = *(const float4*)&A[(rowg * 4 + i) * SA + k0];
            a[i][0] = v.x; a[i][1] = v.y; a[i][2] = v.z; a[i][3] = v.w;
        }
        #pragma unroll
        for (int kk = 0; kk < 4; ++kk) {
            float4 w0 = *(const float4*)&W[(k0 + kk) * 128 + colg * 8];
            float4 w1 = *(const float4*)&W[(k0 + kk) * 128 + colg * 8 + 4];
            float wv[8] = {w0.x, w0.y, w0.z, w0.w, w1.x, w1.y, w1.z, w1.w};
            #pragma unroll
            for (int i = 0; i < 4; ++i)
                #pragma unroll
                for (int j = 0; j < 8; ++j)
                    acc[i][j] += a[i][kk] * wv[j];
        }
    }
    #pragma unroll
    for (int i = 0; i < 4; ++i) {
        float o[8];
        #pragma unroll
        for (int j = 0; j < 8; ++j)
            o[j] = RELU ? fmaxf(acc[i][j], 0.0f) : acc[i][j];
        float* dst = &B[(rowg * 4 + i) * HPAD + colg * 8];
        *(float4*)dst       = make_float4(o[0], o[1], o[2], o[3]);
        *(float4*)(dst + 4) = make_float4(o[4], o[5], o[6], o[7]);
    }
}

__global__ __launch_bounds__(256, 1)
void global_kernel(const float* __restrict__ gW1, const float* __restrict__ gb1,
                   const float* __restrict__ gW2, const float* __restrict__ gb2,
                   const float* __restrict__ gW3, const float* __restrict__ gb3,
                   float* __restrict__ out)
{
    extern __shared__ char raw[];
    Smem2& s = *reinterpret_cast<Smem2*>(raw);
    const int t = threadIdx.x;

    for (int i = t * 4; i < 128 * 128; i += 1024) *(float4*)&s.W1[i] = *(const float4*)&gW1[i];
    for (int i = t * 4; i < 128 * 128; i += 1024) *(float4*)&s.W2[i] = *(const float4*)&gW2[i];
    for (int i = t * 4; i < 128 * 32;  i += 1024) *(float4*)&s.W3[i] = *(const float4*)&gW3[i];
    if (t < 128) { s.b1[t] = gb1[t]; s.b2[t] = gb2[t]; }
    if (t < 32)  { s.b3[t] = gb3[t]; }

    const int seg0 = blockIdx.x * 64;

    for (int i = t * 4; i < 64 * 128; i += 1024) {
        int row = i >> 7, c = i & 127;
        *(float4*)&s.B0[row * HPAD + c] = *(const float4*)&g_agg[(seg0 + row) * EMB + c];
    }
    __syncthreads();

    const int colg = t & 15;
    const int rowg = t >> 4;

    gemm128<128, HPAD, true>(s.B0, s.W1, s.b1, s.B1, rowg, colg);
    __syncthreads();
    gemm128<128, HPAD, true>(s.B1, s.W2, s.b2, s.B0, rowg, colg);
    __syncthreads();

    {
        const int rowg3 = t >> 3;
        const int colg3 = t & 7;
        float acc[2][4];
        {
            float4 bv = *(const float4*)&s.b3[colg3 * 4];
            #pragma unroll
            for (int i = 0; i < 2; ++i) {
                acc[i][0] = bv.x; acc[i][1] = bv.y; acc[i][2] = bv.z; acc[i][3] = bv.w;
            }
        }
        #pragma unroll 2
        for (int k0 = 0; k0 < 128; k0 += 4) {
            float a[2][4];
            #pragma unroll
            for (int i = 0; i < 2; ++i) {
                float4 v = *(const float4*)&s.B0[(rowg3 * 2 + i) * HPAD + k0];
                a[i][0] = v.x; a[i][1] = v.y; a[i][2] = v.z; a[i][3] = v.w;
            }
            #pragma unroll
            for (int kk = 0; kk < 4; ++kk) {
                float4 w = *(const float4*)&s.W3[(k0 + kk) * 32 + colg3 * 4];
                float wv[4] = {w.x, w.y, w.z, w.w};
                #pragma unroll
                for (int i = 0; i < 2; ++i)
                    #pragma unroll
                    for (int j = 0; j < 4; ++j)
                        acc[i][j] += a[i][kk] * wv[j];
            }
        }
        #pragma unroll
        for (int i = 0; i < 2; ++i)
            #pragma unroll
            for (int j = 0; j < 4; ++j)
                s.sc[(rowg3 * 2 + i) * 33 + colg3 * 4 + j] = acc[i][j];
    }
    __syncthreads();

    if (t < 64) {
        float v[32];
        float m = -INFINITY;
        #pragma unroll
        for (int c = 0; c < 32; ++c) { v[c] = s.sc[t * 33 + c]; m = fmaxf(m, v[c]); }
        float sum = 0.0f;
        #pragma unroll
        for (int c = 0; c < 32; ++c) sum += expf(v[c] - m);
        float lse = m + logf(sum);
        float* dst = &out[(size_t)(seg0 + t) * 32];
        #pragma unroll
        for (int c = 0; c < 32; ++c) dst[c] = v[c] - lse;
    }
}

// ---------------------------------------------------------------------------
// Launch
// ---------------------------------------------------------------------------
extern "C" void kernel_launch(void* const* d_in, const int* in_sizes, int n_in,
                              void* d_out, int out_size)
{
    const float* x     = (const float*)d_in[0];
    const int*   index = (const int*)d_in[1];
    const float* lW1 = (const float*)d_in[2];
    const float* lb1 = (const float*)d_in[3];
    const float* lW2 = (const float*)d_in[4];
    const float* lb2 = (const float*)d_in[5];
    const float* lW3 = (const float*)d_in[6];
    const float* lb3 = (const float*)d_in[7];
    const float* gW1 = (const float*)d_in[8];
    const float* gb1 = (const float*)d_in[9];
    const float* gW2 = (const float*)d_in[10];
    const float* gb2 = (const float*)d_in[11];
    const float* gW3 = (const float*)d_in[12];
    const float* gb3 = (const float*)d_in[13];
    float* out = (float*)d_out;

    cudaFuncSetAttribute((const void*)local_mma,
                         cudaFuncAttributeMaxDynamicSharedMemorySize, SM_SZ);
    cudaFuncSetAttribute((const void*)global_kernel,
                         cudaFuncAttributeMaxDynamicSharedMemorySize, (int)sizeof(Smem2));

    zero_agg_kernel<<<(N_SEG * EMB) / 256, 256>>>();
    local_mma<<<148, 512, SM_SZ>>>(x, index, lW1, lb1, lW2, lb2, lW3, lb3);
    global_kernel<<<N_SEG / 64, 256, sizeof(Smem2)>>>(gW1, gb1, gW2, gb2, gW3, gb3, out);
    nop_kernel<<<1, 32>>>();   // shifts ncu -s5 capture window onto local_mma
}